// round 1
// baseline (speedup 1.0000x reference)
#include <cuda_runtime.h>
#include <cstdint>

#define Nn 4096
#define WORDS 128          // 4096 bits / 32
#define TI 8               // i-rows per block (register blocking)
#define JSPLIT 2           // split j-range across blocks for occupancy

// Scratch (device globals — no allocation allowed)
__device__ uint32_t g_bitsT[WORDS * Nn];          // plane-major: word w of row j at [w*Nn + j]
__device__ __align__(16) float g_e[Nn];           // row sums of edge_features
__device__ __align__(16) float g_agg[Nn];         // aggregated[i]

// ---------------------------------------------------------------------------
// K1: bit-pack adjacency with diagonal bit cleared.
// bit t of g_bitsT[w*Nn + j] = (A[j, 32w+t] == 1) && (32w+t != j)
// ---------------------------------------------------------------------------
__global__ void pack_kernel(const float* __restrict__ A) {
    int gw = (blockIdx.x * blockDim.x + threadIdx.x) >> 5;
    int lane = threadIdx.x & 31;
    if (gw >= Nn * WORDS) return;
    int j = gw >> 7;
    int w = gw & (WORDS - 1);
    int col = (w << 5) | lane;
    float v = A[(size_t)j * Nn + col];
    unsigned pred = (v == 1.0f) && (col != j);
    unsigned m = __ballot_sync(0xffffffffu, pred);
    if (lane == 0) g_bitsT[w * Nn + j] = m;
}

// ---------------------------------------------------------------------------
// K2: e[j] = sum_f E[j,f]; also zero g_agg.
// ---------------------------------------------------------------------------
__global__ void rowsum_kernel(const float* __restrict__ E) {
    int j = blockIdx.x;
    const float4* row = (const float4*)(E + (size_t)j * Nn);
    float s = 0.f;
    for (int it = threadIdx.x; it < Nn / 4; it += blockDim.x) {
        float4 v = row[it];
        s += (v.x + v.y) + (v.z + v.w);
    }
    s += __shfl_down_sync(0xffffffffu, s, 16);
    s += __shfl_down_sync(0xffffffffu, s, 8);
    s += __shfl_down_sync(0xffffffffu, s, 4);
    s += __shfl_down_sync(0xffffffffu, s, 2);
    s += __shfl_down_sync(0xffffffffu, s, 1);
    __shared__ float sp[8];
    int lane = threadIdx.x & 31, wid = threadIdx.x >> 5;
    if (lane == 0) sp[wid] = s;
    __syncthreads();
    if (threadIdx.x == 0) {
        float t = 0.f;
        #pragma unroll
        for (int k = 0; k < 8; k++) t += sp[k];
        g_e[j] = t;
        g_agg[j] = 0.f;
    }
}

// ---------------------------------------------------------------------------
// K3: agg[i] = sum_j [ (i!=j) && (B_i & B_j != empty) ] * e[j]
// Fast path: word0 AND != 0  (prob ~1 - 1e-4).  Slow path: scan words 1..127.
// Block handles i-tile of TI rows x a j-chunk of Nn/JSPLIT.
// ---------------------------------------------------------------------------
__global__ void agg_kernel() {
    __shared__ uint32_t sBi[TI * WORDS];
    __shared__ int sNe[TI];           // row nonempty flag (for diag fix)
    __shared__ float sPart[8][TI];
    int tid = threadIdx.x;
    int i0 = blockIdx.x * TI;

    if (tid < TI) sNe[tid] = 0;
    __syncthreads();
    for (int idx = tid; idx < TI * WORDS; idx += blockDim.x) {
        int r = idx >> 7, w = idx & (WORDS - 1);
        uint32_t v = g_bitsT[w * Nn + i0 + r];
        sBi[idx] = v;
        if (v) sNe[r] = 1;            // benign same-value race
    }
    __syncthreads();

    uint32_t bi0[TI];
    float acc[TI];
    #pragma unroll
    for (int r = 0; r < TI; r++) { bi0[r] = sBi[r * WORDS]; acc[r] = 0.f; }

    int jBeg = blockIdx.y * (Nn / JSPLIT);
    int jEnd = jBeg + (Nn / JSPLIT);
    for (int j = jBeg + tid; j < jEnd; j += blockDim.x) {
        uint32_t b0 = g_bitsT[j];     // word-0 plane, L1-resident (16KB)
        float e = g_e[j];
        uint32_t zmask = 0;
        #pragma unroll
        for (int r = 0; r < TI; r++) {
            uint32_t t = bi0[r] & b0;
            if (t) acc[r] += e;
            else   zmask |= (1u << r);
        }
        if (zmask) {                  // rare (~1e-4 per pair)
            do {
                int r = __ffs(zmask) - 1;
                zmask &= zmask - 1;
                bool hit = false;
                for (int w = 1; w < WORDS; w++)
                    if (sBi[r * WORDS + w] & g_bitsT[w * Nn + j]) { hit = true; break; }
                if (hit) acc[r] += e;
            } while (zmask);
        }
        unsigned d = (unsigned)(j - i0);
        if (d < TI && sNe[d]) acc[d] -= e;   // remove bogus j==i contribution
    }

    // block reduction
    int lane = tid & 31, wid = tid >> 5;
    #pragma unroll
    for (int r = 0; r < TI; r++) {
        float v = acc[r];
        v += __shfl_down_sync(0xffffffffu, v, 16);
        v += __shfl_down_sync(0xffffffffu, v, 8);
        v += __shfl_down_sync(0xffffffffu, v, 4);
        v += __shfl_down_sync(0xffffffffu, v, 2);
        v += __shfl_down_sync(0xffffffffu, v, 1);
        if (lane == 0) sPart[wid][r] = v;
    }
    __syncthreads();
    if (tid < TI) {
        float s = 0.f;
        #pragma unroll
        for (int w = 0; w < 8; w++) s += sPart[w][tid];
        atomicAdd(&g_agg[i0 + tid], s);
    }
}

// ---------------------------------------------------------------------------
// K4: out[o] = b[o] + dot(W[o,:], agg)   (one warp per output row)
// ---------------------------------------------------------------------------
__global__ void gemv_kernel(const float* __restrict__ Wm,
                            const float* __restrict__ bias,
                            float* __restrict__ out) {
    int gw = (blockIdx.x * blockDim.x + threadIdx.x) >> 5;
    int lane = threadIdx.x & 31;
    if (gw >= Nn) return;
    const float4* wr = (const float4*)(Wm + (size_t)gw * Nn);
    const float4* ar = (const float4*)g_agg;
    float s = 0.f;
    #pragma unroll 8
    for (int it = lane; it < Nn / 4; it += 32) {
        float4 v = wr[it];
        float4 a = ar[it];
        s += v.x * a.x + v.y * a.y + v.z * a.z + v.w * a.w;
    }
    s += __shfl_down_sync(0xffffffffu, s, 16);
    s += __shfl_down_sync(0xffffffffu, s, 8);
    s += __shfl_down_sync(0xffffffffu, s, 4);
    s += __shfl_down_sync(0xffffffffu, s, 2);
    s += __shfl_down_sync(0xffffffffu, s, 1);
    if (lane == 0) out[gw] = s + bias[gw];
}

extern "C" void kernel_launch(void* const* d_in, const int* in_sizes, int n_in,
                              void* d_out, int out_size) {
    const float* A  = (const float*)d_in[0];  // adjacency [N,N]
    const float* E  = (const float*)d_in[1];  // edge_features [N,F]
    const float* Wm = (const float*)d_in[2];  // W [OUT,N]
    const float* b  = (const float*)d_in[3];  // b [OUT]
    float* out = (float*)d_out;

    pack_kernel<<<(Nn * WORDS * 32) / 256, 256>>>(A);
    rowsum_kernel<<<Nn, 256>>>(E);
    dim3 g3(Nn / TI, JSPLIT);
    agg_kernel<<<g3, 256>>>();
    gemv_kernel<<<(Nn * 32) / 256, 256>>>(Wm, b, out);
}

// round 2
// speedup vs baseline: 1.2362x; 1.2362x over previous
#include <cuda_runtime.h>
#include <cstdint>

#define Nn 4096
#define WORDS 128          // 4096 bits / 32
#define TI 16              // i-rows per block (register blocking)
#define JSPLIT 2           // split j-range across blocks
#define PACK_BLOCKS 2048
#define ROWSUM_BLOCKS Nn
#define PREF_BLOCKS 256    // L2-prefetch blocks for W inside agg launch

// Scratch (device globals — no allocation allowed)
__device__ uint32_t g_bitsT[WORDS * Nn];   // plane-major: word w of row j at [w*Nn + j]
__device__ __align__(16) float g_e[Nn];    // row sums of edge_features
__device__ __align__(16) float g_agg[Nn];  // aggregated[i]
__device__ float g_sink[PREF_BLOCKS];      // prefetch sink (never read)

// ---------------------------------------------------------------------------
// K1 (fused): blocks [0, PACK_BLOCKS) bit-pack adjacency (diag bit cleared);
//             blocks [PACK_BLOCKS, PACK_BLOCKS+Nn) row-sum E and zero g_agg.
// Both are pure DRAM streams; fusing keeps HBM saturated across the 128MB.
// ---------------------------------------------------------------------------
__global__ void prep_kernel(const float* __restrict__ A,
                            const float* __restrict__ E) {
    if (blockIdx.x < PACK_BLOCKS) {
        int lane = threadIdx.x & 31;
        int gwid = blockIdx.x * (blockDim.x >> 5) + (threadIdx.x >> 5);
        int nwarps = PACK_BLOCKS * (blockDim.x >> 5);
        for (int gw = gwid; gw < Nn * WORDS; gw += nwarps) {
            int j = gw >> 7;
            int w = gw & (WORDS - 1);
            int col = (w << 5) | lane;
            float v = A[(size_t)j * Nn + col];
            unsigned pred = (v == 1.0f) && (col != j);
            unsigned m = __ballot_sync(0xffffffffu, pred);
            if (lane == 0) g_bitsT[w * Nn + j] = m;
        }
    } else {
        int j = blockIdx.x - PACK_BLOCKS;
        const float4* row = (const float4*)(E + (size_t)j * Nn);
        int tid = threadIdx.x;
        float s = 0.f;
        #pragma unroll
        for (int k = 0; k < 4; k++) {
            float4 v = row[tid + 256 * k];
            s += (v.x + v.y) + (v.z + v.w);
        }
        s += __shfl_down_sync(0xffffffffu, s, 16);
        s += __shfl_down_sync(0xffffffffu, s, 8);
        s += __shfl_down_sync(0xffffffffu, s, 4);
        s += __shfl_down_sync(0xffffffffu, s, 2);
        s += __shfl_down_sync(0xffffffffu, s, 1);
        __shared__ float sp[8];
        int lane = tid & 31, wid = tid >> 5;
        if (lane == 0) sp[wid] = s;
        __syncthreads();
        if (tid == 0) {
            float t = 0.f;
            #pragma unroll
            for (int k = 0; k < 8; k++) t += sp[k];
            g_e[j] = t;
            g_agg[j] = 0.f;
        }
    }
}

// ---------------------------------------------------------------------------
// K2: agg[i] = sum_j [ (i!=j) && (B_i & B_j != empty) ] * e[j]
// Fast path: word0 AND != 0 (miss prob ~1e-4). Slow path: scan words 1..127.
// blockIdx.y == 0: prefetch W into L2 (DRAM is otherwise idle here).
// blockIdx.y in {1,2}: compute, i-tile of TI rows x a j-chunk of Nn/JSPLIT.
// ---------------------------------------------------------------------------
__global__ void agg_kernel(const float* __restrict__ Wm) {
    int tid = threadIdx.x;

    if (blockIdx.y == 0) {
        if (blockIdx.x >= PREF_BLOCKS) return;
        // stream a 256KB slice of W through LDG -> fills L2
        const float4* w4 = (const float4*)Wm;
        size_t base = (size_t)blockIdx.x * (Nn * Nn / 4 / PREF_BLOCKS) + tid;
        float s0 = 0.f, s1 = 0.f, s2 = 0.f, s3 = 0.f;
        #pragma unroll
        for (int k = 0; k < 64; k += 4) {
            float4 a = w4[base + (size_t)(k + 0) * 256];
            float4 b = w4[base + (size_t)(k + 1) * 256];
            float4 c = w4[base + (size_t)(k + 2) * 256];
            float4 d = w4[base + (size_t)(k + 3) * 256];
            s0 += a.x + a.y + a.z + a.w;
            s1 += b.x + b.y + b.z + b.w;
            s2 += c.x + c.y + c.z + c.w;
            s3 += d.x + d.y + d.z + d.w;
        }
        float s = (s0 + s1) + (s2 + s3);
        if (tid == 0) g_sink[blockIdx.x] = s;   // keep the loads live
        return;
    }

    __shared__ uint32_t sBi[TI * WORDS];
    __shared__ int sNe[TI];           // row-nonempty flag (for diag fix)
    __shared__ float sPart[8][TI];
    int i0 = blockIdx.x * TI;

    if (tid < TI) sNe[tid] = 0;
    __syncthreads();
    for (int idx = tid; idx < TI * WORDS; idx += blockDim.x) {
        int r = idx >> 7, w = idx & (WORDS - 1);
        uint32_t v = g_bitsT[w * Nn + i0 + r];
        sBi[idx] = v;
        if (v) sNe[r] = 1;            // benign same-value race
    }
    __syncthreads();

    uint32_t bi0[TI];
    float acc[TI];
    #pragma unroll
    for (int r = 0; r < TI; r++) { bi0[r] = sBi[r * WORDS]; acc[r] = 0.f; }

    int jBeg = (blockIdx.y - 1) * (Nn / JSPLIT);
    int jEnd = jBeg + (Nn / JSPLIT);
    for (int j = jBeg + tid; j < jEnd; j += blockDim.x) {
        uint32_t b0 = g_bitsT[j];     // word-0 plane: 16KB, cache-resident
        float e = g_e[j];
        unsigned zmask = 0;
        #pragma unroll
        for (int r = 0; r < TI; r++) {
            uint32_t t = bi0[r] & b0;
            if (t) acc[r] += e;
            else   zmask |= (1u << r);
        }
        if (zmask) {                  // rare (~1e-4 per pair)
            do {
                int r = __ffs(zmask) - 1;
                zmask &= zmask - 1;
                bool hit = false;
                for (int w = 1; w < WORDS; w++)
                    if (sBi[r * WORDS + w] & g_bitsT[w * Nn + j]) { hit = true; break; }
                if (hit) acc[r] += e;
            } while (zmask);
        }
        unsigned d = (unsigned)(j - i0);
        if (d < TI && sNe[d]) acc[d] -= e;   // remove bogus j==i contribution
    }

    int lane = tid & 31, wid = tid >> 5;
    #pragma unroll
    for (int r = 0; r < TI; r++) {
        float v = acc[r];
        v += __shfl_down_sync(0xffffffffu, v, 16);
        v += __shfl_down_sync(0xffffffffu, v, 8);
        v += __shfl_down_sync(0xffffffffu, v, 4);
        v += __shfl_down_sync(0xffffffffu, v, 2);
        v += __shfl_down_sync(0xffffffffu, v, 1);
        if (lane == 0) sPart[wid][r] = v;
    }
    __syncthreads();
    if (tid < TI) {
        float s = 0.f;
        #pragma unroll
        for (int w = 0; w < 8; w++) s += sPart[w][tid];
        atomicAdd(&g_agg[i0 + tid], s);
    }
}

// ---------------------------------------------------------------------------
// K3: out[o] = b[o] + dot(W[o,:], agg)   (one warp per row; W is L2-hot)
// ---------------------------------------------------------------------------
__global__ void gemv_kernel(const float* __restrict__ Wm,
                            const float* __restrict__ bias,
                            float* __restrict__ out) {
    int gw = (blockIdx.x * blockDim.x + threadIdx.x) >> 5;
    int lane = threadIdx.x & 31;
    if (gw >= Nn) return;
    const float4* wr = (const float4*)(Wm + (size_t)gw * Nn);
    const float4* ar = (const float4*)g_agg;
    float s0 = 0.f, s1 = 0.f, s2 = 0.f, s3 = 0.f;
    #pragma unroll
    for (int k = 0; k < 32; k += 4) {
        float4 w0 = wr[lane + 32 * (k + 0)];
        float4 w1 = wr[lane + 32 * (k + 1)];
        float4 w2 = wr[lane + 32 * (k + 2)];
        float4 w3 = wr[lane + 32 * (k + 3)];
        float4 a0 = ar[lane + 32 * (k + 0)];
        float4 a1 = ar[lane + 32 * (k + 1)];
        float4 a2 = ar[lane + 32 * (k + 2)];
        float4 a3 = ar[lane + 32 * (k + 3)];
        s0 += w0.x * a0.x + w0.y * a0.y + w0.z * a0.z + w0.w * a0.w;
        s1 += w1.x * a1.x + w1.y * a1.y + w1.z * a1.z + w1.w * a1.w;
        s2 += w2.x * a2.x + w2.y * a2.y + w2.z * a2.z + w2.w * a2.w;
        s3 += w3.x * a3.x + w3.y * a3.y + w3.z * a3.z + w3.w * a3.w;
    }
    float s = (s0 + s1) + (s2 + s3);
    s += __shfl_down_sync(0xffffffffu, s, 16);
    s += __shfl_down_sync(0xffffffffu, s, 8);
    s += __shfl_down_sync(0xffffffffu, s, 4);
    s += __shfl_down_sync(0xffffffffu, s, 2);
    s += __shfl_down_sync(0xffffffffu, s, 1);
    if (lane == 0) out[gw] = s + bias[gw];
}

extern "C" void kernel_launch(void* const* d_in, const int* in_sizes, int n_in,
                              void* d_out, int out_size) {
    const float* A  = (const float*)d_in[0];  // adjacency [N,N]
    const float* E  = (const float*)d_in[1];  // edge_features [N,F]
    const float* Wm = (const float*)d_in[2];  // W [OUT,N]
    const float* b  = (const float*)d_in[3];  // b [OUT]
    float* out = (float*)d_out;

    prep_kernel<<<PACK_BLOCKS + ROWSUM_BLOCKS, 256>>>(A, E);
    dim3 g2(Nn / TI, JSPLIT + 1);             // y==0: W prefetch; y==1,2: compute
    agg_kernel<<<g2, 256>>>(Wm);
    gemv_kernel<<<(Nn * 32) / 256, 256>>>(Wm, b, out);
}

// round 3
// speedup vs baseline: 1.2434x; 1.0058x over previous
#include <cuda_runtime.h>
#include <cstdint>

#define Nn 4096
#define WORDS 128          // 4096 bits / 32
#define TI 16              // i-rows per block (register blocking)
#define JSPLIT 2           // split j-range across blocks
#define PACK_BLOCKS 2048
#define ROWSUM_BLOCKS Nn
#define PREF_BLOCKS 256    // L2-prefetch blocks for W inside agg launch

// Scratch (device globals — no allocation allowed)
__device__ uint32_t g_bitsT[WORDS * Nn];   // plane-major: word w of row j at [w*Nn + j]
__device__ __align__(16) float g_e[Nn];    // row sums of edge_features
__device__ __align__(16) float g_agg[Nn];  // aggregated[i]
__device__ float g_sink[PREF_BLOCKS];      // prefetch sink (never read)

// ---------------------------------------------------------------------------
// K1 (fused): blocks [0, PACK_BLOCKS) bit-pack adjacency (diag bit cleared);
//             blocks [PACK_BLOCKS, PACK_BLOCKS+Nn) row-sum E and zero g_agg.
// Both are pure DRAM streams; fusing keeps HBM saturated across the 128MB.
// ---------------------------------------------------------------------------
__global__ void prep_kernel(const float* __restrict__ A,
                            const float* __restrict__ E) {
    if (blockIdx.x < PACK_BLOCKS) {
        int lane = threadIdx.x & 31;
        int gwid = blockIdx.x * (blockDim.x >> 5) + (threadIdx.x >> 5);
        int nwarps = PACK_BLOCKS * (blockDim.x >> 5);
        for (int gw = gwid; gw < Nn * WORDS; gw += nwarps) {
            int j = gw >> 7;
            int w = gw & (WORDS - 1);
            int col = (w << 5) | lane;
            float v = A[(size_t)j * Nn + col];
            unsigned pred = (v == 1.0f) && (col != j);
            unsigned m = __ballot_sync(0xffffffffu, pred);
            if (lane == 0) g_bitsT[w * Nn + j] = m;
        }
    } else {
        int j = blockIdx.x - PACK_BLOCKS;
        const float4* row = (const float4*)(E + (size_t)j * Nn);
        int tid = threadIdx.x;
        float s = 0.f;
        #pragma unroll
        for (int k = 0; k < 4; k++) {
            float4 v = row[tid + 256 * k];
            s += (v.x + v.y) + (v.z + v.w);
        }
        s += __shfl_down_sync(0xffffffffu, s, 16);
        s += __shfl_down_sync(0xffffffffu, s, 8);
        s += __shfl_down_sync(0xffffffffu, s, 4);
        s += __shfl_down_sync(0xffffffffu, s, 2);
        s += __shfl_down_sync(0xffffffffu, s, 1);
        __shared__ float sp[8];
        int lane = tid & 31, wid = tid >> 5;
        if (lane == 0) sp[wid] = s;
        __syncthreads();
        if (tid == 0) {
            float t = 0.f;
            #pragma unroll
            for (int k = 0; k < 8; k++) t += sp[k];
            g_e[j] = t;
            g_agg[j] = 0.f;
        }
    }
}

// ---------------------------------------------------------------------------
// K2: agg[i] = sum_j [ (i!=j) && (B_i & B_j != empty) ] * e[j]
// Fast path: word0 AND != 0 (miss prob ~1e-4). Slow path: scan words 1..127.
// blockIdx.y == 0: prefetch W into L2 (DRAM is otherwise idle here).
// blockIdx.y in {1,2}: compute, i-tile of TI rows x a j-chunk of Nn/JSPLIT.
// ---------------------------------------------------------------------------
__global__ void agg_kernel(const float* __restrict__ Wm) {
    int tid = threadIdx.x;

    if (blockIdx.y == 0) {
        if (blockIdx.x >= PREF_BLOCKS) return;
        // stream a 256KB slice of W through LDG -> fills L2
        const float4* w4 = (const float4*)Wm;
        size_t base = (size_t)blockIdx.x * (Nn * Nn / 4 / PREF_BLOCKS) + tid;
        float s0 = 0.f, s1 = 0.f, s2 = 0.f, s3 = 0.f;
        #pragma unroll
        for (int k = 0; k < 64; k += 4) {
            float4 a = w4[base + (size_t)(k + 0) * 256];
            float4 b = w4[base + (size_t)(k + 1) * 256];
            float4 c = w4[base + (size_t)(k + 2) * 256];
            float4 d = w4[base + (size_t)(k + 3) * 256];
            s0 += a.x + a.y + a.z + a.w;
            s1 += b.x + b.y + b.z + b.w;
            s2 += c.x + c.y + c.z + c.w;
            s3 += d.x + d.y + d.z + d.w;
        }
        float s = (s0 + s1) + (s2 + s3);
        if (tid == 0) g_sink[blockIdx.x] = s;   // keep the loads live
        return;
    }

    __shared__ uint32_t sBi[TI * WORDS];
    __shared__ int sNe[TI];           // row-nonempty flag (for diag fix)
    __shared__ float sPart[8][TI];
    int i0 = blockIdx.x * TI;

    if (tid < TI) sNe[tid] = 0;
    __syncthreads();
    for (int idx = tid; idx < TI * WORDS; idx += blockDim.x) {
        int r = idx >> 7, w = idx & (WORDS - 1);
        uint32_t v = g_bitsT[w * Nn + i0 + r];
        sBi[idx] = v;
        if (v) sNe[r] = 1;            // benign same-value race
    }
    __syncthreads();

    uint32_t bi0[TI];
    float acc[TI];
    #pragma unroll
    for (int r = 0; r < TI; r++) { bi0[r] = sBi[r * WORDS]; acc[r] = 0.f; }

    int jBeg = (blockIdx.y - 1) * (Nn / JSPLIT);
    int jEnd = jBeg + (Nn / JSPLIT);
    for (int j = jBeg + tid; j < jEnd; j += blockDim.x) {
        uint32_t b0 = g_bitsT[j];     // word-0 plane: 16KB, cache-resident
        float e = g_e[j];
        unsigned zmask = 0;
        #pragma unroll
        for (int r = 0; r < TI; r++) {
            uint32_t t = bi0[r] & b0;
            if (t) acc[r] += e;
            else   zmask |= (1u << r);
        }
        if (zmask) {                  // rare (~1e-4 per pair)
            do {
                int r = __ffs(zmask) - 1;
                zmask &= zmask - 1;
                bool hit = false;
                for (int w = 1; w < WORDS; w++)
                    if (sBi[r * WORDS + w] & g_bitsT[w * Nn + j]) { hit = true; break; }
                if (hit) acc[r] += e;
            } while (zmask);
        }
        unsigned d = (unsigned)(j - i0);
        if (d < TI && sNe[d]) acc[d] -= e;   // remove bogus j==i contribution
    }

    int lane = tid & 31, wid = tid >> 5;
    #pragma unroll
    for (int r = 0; r < TI; r++) {
        float v = acc[r];
        v += __shfl_down_sync(0xffffffffu, v, 16);
        v += __shfl_down_sync(0xffffffffu, v, 8);
        v += __shfl_down_sync(0xffffffffu, v, 4);
        v += __shfl_down_sync(0xffffffffu, v, 2);
        v += __shfl_down_sync(0xffffffffu, v, 1);
        if (lane == 0) sPart[wid][r] = v;
    }
    __syncthreads();
    if (tid < TI) {
        float s = 0.f;
        #pragma unroll
        for (int w = 0; w < 8; w++) s += sPart[w][tid];
        atomicAdd(&g_agg[i0 + tid], s);
    }
}

// ---------------------------------------------------------------------------
// K3: out[o] = b[o] + dot(W[o,:], agg)   (one warp per row; W is L2-hot)
// ---------------------------------------------------------------------------
__global__ void gemv_kernel(const float* __restrict__ Wm,
                            const float* __restrict__ bias,
                            float* __restrict__ out) {
    int gw = (blockIdx.x * blockDim.x + threadIdx.x) >> 5;
    int lane = threadIdx.x & 31;
    if (gw >= Nn) return;
    const float4* wr = (const float4*)(Wm + (size_t)gw * Nn);
    const float4* ar = (const float4*)g_agg;
    float s0 = 0.f, s1 = 0.f, s2 = 0.f, s3 = 0.f;
    #pragma unroll
    for (int k = 0; k < 32; k += 4) {
        float4 w0 = wr[lane + 32 * (k + 0)];
        float4 w1 = wr[lane + 32 * (k + 1)];
        float4 w2 = wr[lane + 32 * (k + 2)];
        float4 w3 = wr[lane + 32 * (k + 3)];
        float4 a0 = ar[lane + 32 * (k + 0)];
        float4 a1 = ar[lane + 32 * (k + 1)];
        float4 a2 = ar[lane + 32 * (k + 2)];
        float4 a3 = ar[lane + 32 * (k + 3)];
        s0 += w0.x * a0.x + w0.y * a0.y + w0.z * a0.z + w0.w * a0.w;
        s1 += w1.x * a1.x + w1.y * a1.y + w1.z * a1.z + w1.w * a1.w;
        s2 += w2.x * a2.x + w2.y * a2.y + w2.z * a2.z + w2.w * a2.w;
        s3 += w3.x * a3.x + w3.y * a3.y + w3.z * a3.z + w3.w * a3.w;
    }
    float s = (s0 + s1) + (s2 + s3);
    s += __shfl_down_sync(0xffffffffu, s, 16);
    s += __shfl_down_sync(0xffffffffu, s, 8);
    s += __shfl_down_sync(0xffffffffu, s, 4);
    s += __shfl_down_sync(0xffffffffu, s, 2);
    s += __shfl_down_sync(0xffffffffu, s, 1);
    if (lane == 0) out[gw] = s + bias[gw];
}

extern "C" void kernel_launch(void* const* d_in, const int* in_sizes, int n_in,
                              void* d_out, int out_size) {
    const float* A  = (const float*)d_in[0];  // adjacency [N,N]
    const float* E  = (const float*)d_in[1];  // edge_features [N,F]
    const float* Wm = (const float*)d_in[2];  // W [OUT,N]
    const float* b  = (const float*)d_in[3];  // b [OUT]
    float* out = (float*)d_out;

    prep_kernel<<<PACK_BLOCKS + ROWSUM_BLOCKS, 256>>>(A, E);
    dim3 g2(Nn / TI, JSPLIT + 1);             // y==0: W prefetch; y==1,2: compute
    agg_kernel<<<g2, 256>>>(Wm);
    gemv_kernel<<<(Nn * 32) / 256, 256>>>(Wm, b, out);
}

// round 4
// speedup vs baseline: 1.3301x; 1.0697x over previous
#include <cuda_runtime.h>
#include <cstdint>

#define Nn 4096
#define WORDS 128          // 4096 bits / 32
#define TI 16              // i-rows per block (register blocking)
#define JSPLIT 2           // split j-range across blocks
#define PACK_BLOCKS 2048
#define ROWSUM_BLOCKS Nn
#define PREF_BLOCKS 256    // L2-prefetch blocks for W inside agg launch

// Scratch (device globals — no allocation allowed)
__device__ uint32_t g_bitsT[WORDS * Nn];   // plane-major: word w of row j at [w*Nn + j]
__device__ uint32_t g_h2[Nn * 2];          // per-row head: words 0,1 contiguous (uint2 view)
__device__ __align__(16) float g_e[Nn];    // row sums of edge_features
__device__ __align__(16) float g_agg[Nn];  // aggregated[i]
__device__ float g_sink[PREF_BLOCKS];      // prefetch sink (never read)

// ---------------------------------------------------------------------------
// K1 (fused): blocks [0, PACK_BLOCKS) bit-pack adjacency (diag bit cleared)
//   — float4 loads (4 cols/thread), nibble -> word via __reduce_or_sync over
//     8-lane groups. 512B in flight per warp-iter (4x the old LDG.32 path).
// blocks [PACK_BLOCKS, ...) row-sum E and zero g_agg.
// ---------------------------------------------------------------------------
__global__ void prep_kernel(const float* __restrict__ A,
                            const float* __restrict__ E) {
    if (blockIdx.x < PACK_BLOCKS) {
        int lane = threadIdx.x & 31;
        int gwid = blockIdx.x * 8 + (threadIdx.x >> 5);
        const int NWG = Nn * (WORDS / 4);      // j x 128-col groups
        const int STRIDE = PACK_BLOCKS * 8;
        unsigned q = lane >> 3;                // word index within the group
        unsigned grpmask = 0xFFu << (q * 8);
        unsigned sh = (lane & 7) * 4;
        #pragma unroll 4
        for (int gw = gwid; gw < NWG; gw += STRIDE) {
            int j  = gw >> 5;
            int wg = gw & 31;
            int col = (wg << 7) + (lane << 2);
            float4 v = *(const float4*)(A + (size_t)j * Nn + col);
            unsigned nib = 0;
            if (v.x == 1.0f && col + 0 != j) nib |= 1u;
            if (v.y == 1.0f && col + 1 != j) nib |= 2u;
            if (v.z == 1.0f && col + 2 != j) nib |= 4u;
            if (v.w == 1.0f && col + 3 != j) nib |= 8u;
            unsigned word = __reduce_or_sync(grpmask, nib << sh);
            if ((lane & 7) == 0) {
                int w = (wg << 2) + q;
                g_bitsT[w * Nn + j] = word;
                if (w < 2) g_h2[j * 2 + w] = word;
            }
        }
    } else {
        int j = blockIdx.x - PACK_BLOCKS;
        const float4* row = (const float4*)(E + (size_t)j * Nn);
        int tid = threadIdx.x;
        float s = 0.f;
        #pragma unroll
        for (int k = 0; k < 4; k++) {
            float4 v = row[tid + 256 * k];
            s += (v.x + v.y) + (v.z + v.w);
        }
        s += __shfl_down_sync(0xffffffffu, s, 16);
        s += __shfl_down_sync(0xffffffffu, s, 8);
        s += __shfl_down_sync(0xffffffffu, s, 4);
        s += __shfl_down_sync(0xffffffffu, s, 2);
        s += __shfl_down_sync(0xffffffffu, s, 1);
        __shared__ float sp[8];
        int lane = tid & 31, wid = tid >> 5;
        if (lane == 0) sp[wid] = s;
        __syncthreads();
        if (tid == 0) {
            float t = 0.f;
            #pragma unroll
            for (int k = 0; k < 8; k++) t += sp[k];
            g_e[j] = t;
            g_agg[j] = 0.f;
        }
    }
}

// ---------------------------------------------------------------------------
// K2: agg[i] = sum_j [ (i!=j) && (B_i & B_j != empty) ] * e[j]
// Fast path: 64-bit head AND (words 0-1), miss prob e^-4 ~ 1.8%.
// Slow path: scan words 2..127 (i-side from shared, j-side from L2).
// blockIdx.y == 0: prefetch W into L2 (DRAM is otherwise idle here).
// ---------------------------------------------------------------------------
__global__ void agg_kernel(const float* __restrict__ Wm) {
    int tid = threadIdx.x;

    if (blockIdx.y == 0) {
        if (blockIdx.x >= PREF_BLOCKS) return;
        const float4* w4 = (const float4*)Wm;
        size_t base = (size_t)blockIdx.x * (Nn * Nn / 4 / PREF_BLOCKS) + tid;
        float s0 = 0.f, s1 = 0.f, s2 = 0.f, s3 = 0.f;
        #pragma unroll
        for (int k = 0; k < 64; k += 4) {
            float4 a = w4[base + (size_t)(k + 0) * 256];
            float4 b = w4[base + (size_t)(k + 1) * 256];
            float4 c = w4[base + (size_t)(k + 2) * 256];
            float4 d = w4[base + (size_t)(k + 3) * 256];
            s0 += a.x + a.y + a.z + a.w;
            s1 += b.x + b.y + b.z + b.w;
            s2 += c.x + c.y + c.z + c.w;
            s3 += d.x + d.y + d.z + d.w;
        }
        float s = (s0 + s1) + (s2 + s3);
        if (tid == 0) g_sink[blockIdx.x] = s;   // keep the loads live
        return;
    }

    __shared__ uint32_t sBi[TI * WORDS];
    __shared__ int sNe[TI];           // row-nonempty flag (for diag fix)
    __shared__ float sPart[8][TI];
    int i0 = blockIdx.x * TI;

    if (tid < TI) sNe[tid] = 0;
    __syncthreads();
    for (int idx = tid; idx < TI * WORDS; idx += blockDim.x) {
        int r = idx >> 7, w = idx & (WORDS - 1);
        uint32_t v = g_bitsT[w * Nn + i0 + r];
        sBi[idx] = v;
        if (v) sNe[r] = 1;            // benign same-value race
    }
    __syncthreads();

    uint32_t bi0[TI], bi1[TI];
    float acc[TI];
    #pragma unroll
    for (int r = 0; r < TI; r++) {
        bi0[r] = sBi[r * WORDS];
        bi1[r] = sBi[r * WORDS + 1];
        acc[r] = 0.f;
    }

    const uint2* h2 = (const uint2*)g_h2;
    int jBeg = (blockIdx.y - 1) * (Nn / JSPLIT);
    int jEnd = jBeg + (Nn / JSPLIT);
    for (int j = jBeg + tid; j < jEnd; j += blockDim.x) {
        uint2 h = h2[j];              // 32KB head plane, cache-resident
        float e = g_e[j];
        unsigned zmask = 0;
        #pragma unroll
        for (int r = 0; r < TI; r++) {
            uint32_t t = (bi0[r] & h.x) | (bi1[r] & h.y);
            if (t) acc[r] += e;
            else   zmask |= (1u << r);
        }
        if (zmask) {                  // rare (~1.8% per pair)
            do {
                int r = __ffs(zmask) - 1;
                zmask &= zmask - 1;
                bool hit = false;
                for (int w = 2; w < WORDS; w++)
                    if (sBi[r * WORDS + w] & g_bitsT[w * Nn + j]) { hit = true; break; }
                if (hit) acc[r] += e;
            } while (zmask);
        }
        unsigned d = (unsigned)(j - i0);
        if (d < TI && sNe[d]) acc[d] -= e;   // remove bogus j==i contribution
    }

    int lane = tid & 31, wid = tid >> 5;
    #pragma unroll
    for (int r = 0; r < TI; r++) {
        float v = acc[r];
        v += __shfl_down_sync(0xffffffffu, v, 16);
        v += __shfl_down_sync(0xffffffffu, v, 8);
        v += __shfl_down_sync(0xffffffffu, v, 4);
        v += __shfl_down_sync(0xffffffffu, v, 2);
        v += __shfl_down_sync(0xffffffffu, v, 1);
        if (lane == 0) sPart[wid][r] = v;
    }
    __syncthreads();
    if (tid < TI) {
        float s = 0.f;
        #pragma unroll
        for (int w = 0; w < 8; w++) s += sPart[w][tid];
        atomicAdd(&g_agg[i0 + tid], s);
    }
}

// ---------------------------------------------------------------------------
// K3: out[o] = b[o] + dot(W[o,:], agg)   (one warp per row; W is L2-hot)
// ---------------------------------------------------------------------------
__global__ void gemv_kernel(const float* __restrict__ Wm,
                            const float* __restrict__ bias,
                            float* __restrict__ out) {
    int gw = (blockIdx.x * blockDim.x + threadIdx.x) >> 5;
    int lane = threadIdx.x & 31;
    if (gw >= Nn) return;
    const float4* wr = (const float4*)(Wm + (size_t)gw * Nn);
    const float4* ar = (const float4*)g_agg;
    float s0 = 0.f, s1 = 0.f, s2 = 0.f, s3 = 0.f;
    #pragma unroll
    for (int k = 0; k < 32; k += 4) {
        float4 w0 = wr[lane + 32 * (k + 0)];
        float4 w1 = wr[lane + 32 * (k + 1)];
        float4 w2 = wr[lane + 32 * (k + 2)];
        float4 w3 = wr[lane + 32 * (k + 3)];
        float4 a0 = ar[lane + 32 * (k + 0)];
        float4 a1 = ar[lane + 32 * (k + 1)];
        float4 a2 = ar[lane + 32 * (k + 2)];
        float4 a3 = ar[lane + 32 * (k + 3)];
        s0 += w0.x * a0.x + w0.y * a0.y + w0.z * a0.z + w0.w * a0.w;
        s1 += w1.x * a1.x + w1.y * a1.y + w1.z * a1.z + w1.w * a1.w;
        s2 += w2.x * a2.x + w2.y * a2.y + w2.z * a2.z + w2.w * a2.w;
        s3 += w3.x * a3.x + w3.y * a3.y + w3.z * a3.z + w3.w * a3.w;
    }
    float s = (s0 + s1) + (s2 + s3);
    s += __shfl_down_sync(0xffffffffu, s, 16);
    s += __shfl_down_sync(0xffffffffu, s, 8);
    s += __shfl_down_sync(0xffffffffu, s, 4);
    s += __shfl_down_sync(0xffffffffu, s, 2);
    s += __shfl_down_sync(0xffffffffu, s, 1);
    if (lane == 0) out[gw] = s + bias[gw];
}

extern "C" void kernel_launch(void* const* d_in, const int* in_sizes, int n_in,
                              void* d_out, int out_size) {
    const float* A  = (const float*)d_in[0];  // adjacency [N,N]
    const float* E  = (const float*)d_in[1];  // edge_features [N,F]
    const float* Wm = (const float*)d_in[2];  // W [OUT,N]
    const float* b  = (const float*)d_in[3];  // b [OUT]
    float* out = (float*)d_out;

    prep_kernel<<<PACK_BLOCKS + ROWSUM_BLOCKS, 256>>>(A, E);
    dim3 g2(Nn / TI, JSPLIT + 1);             // y==0: W prefetch; y==1,2: compute
    agg_kernel<<<g2, 256>>>(Wm);
    gemv_kernel<<<(Nn * 32) / 256, 256>>>(Wm, b, out);
}